// round 10
// baseline (speedup 1.0000x reference)
#include <cuda_runtime.h>

#define NROWS  8192
#define DCOLS  4096
#define MARGINF 5.0f
#define MAXLIST 2048
#define DTHREADS 256

// Scratch. Initial values match the post-run reset done by the last block,
// so every graph replay starts from identical state.
__device__ float        g_d[NROWS];
__device__ double       g_sp = 0.0;             // sum of pos distances
__device__ double       g_sn = 0.0;             // sum of neg distances
__device__ int          g_np = 0;               // pos count
__device__ int          g_minpos = 0x7f800000;  // +inf bits (pos-float ordering)
__device__ int          g_maxneg = 0;           // 0.0f bits
__device__ unsigned int g_ticket = 0u;

// One block per row: d = sqrt(sum (recon-x)^2) + 0.001 with fused global
// stats atomics. The LAST block (fence+ticket) finalizes in its tail:
//   Sum_{i pos, j neg} max(0, d_i - d_j + M)
// = [Nn*Sp - Np*Sn + M*Np*Nn] + Sum max(0, d_j - d_i - M)
// Correction candidates: pos with d_i < max_neg - M, neg with d_j > min_pos + M
// (~330 each expected); exact cross product, pos-striped across threads.
__global__ __launch_bounds__(DTHREADS) void dist_kernel(
    const float* __restrict__ recon, const float* __restrict__ x,
    const int* __restrict__ targets, float* __restrict__ out)
{
    const int row = blockIdx.x;
    const int tid = threadIdx.x;
    const float4* r4 = reinterpret_cast<const float4*>(recon + (size_t)row * DCOLS);
    const float4* x4 = reinterpret_cast<const float4*>(x + (size_t)row * DCOLS);

    float acc = 0.0f;
    #pragma unroll 4
    for (int k = tid; k < DCOLS / 4; k += DTHREADS) {
        float4 a = r4[k];
        float4 b = x4[k];
        float d0 = a.x - b.x;
        float d1 = a.y - b.y;
        float d2 = a.z - b.z;
        float d3 = a.w - b.w;
        acc = fmaf(d0, d0, acc);
        acc = fmaf(d1, d1, acc);
        acc = fmaf(d2, d2, acc);
        acc = fmaf(d3, d3, acc);
    }

    #pragma unroll
    for (int o = 16; o > 0; o >>= 1)
        acc += __shfl_xor_sync(0xFFFFFFFFu, acc, o);

    __shared__ float ws[8];
    __shared__ int   s_last;
    if ((tid & 31) == 0) ws[tid >> 5] = acc;
    __syncthreads();

    if (tid == 0) {
        float s = 0.0f;
        #pragma unroll
        for (int w = 0; w < 8; w++) s += ws[w];
        float d = sqrtf(s) + 0.001f;
        g_d[row] = d;
        int bits = __float_as_int(d);   // positive floats: int order == float order
        if (targets[row] == 1) {
            atomicAdd(&g_sp, (double)d);
            atomicMin(&g_minpos, bits);
            atomicAdd(&g_np, 1);
        } else {
            atomicAdd(&g_sn, (double)d);
            atomicMax(&g_maxneg, bits);
        }
        __threadfence();
        unsigned int t = atomicAdd(&g_ticket, 1u);
        s_last = (t == NROWS - 1);
    }
    __syncthreads();
    if (!s_last) return;

    // ================= last block: fused finalize =================
    __shared__ float  posList[MAXLIST], negList[MAXLIST];
    __shared__ int    s_npl, s_nnl;
    __shared__ double redC[8];

    if (tid == 0) { s_npl = 0; s_nnl = 0; }
    __syncthreads();

    const float minpos = __int_as_float(g_minpos);
    const float maxneg = __int_as_float(g_maxneg);
    const float thrP = maxneg - MARGINF;   // pos matter if d_i < thrP
    const float thrN = minpos + MARGINF;   // neg matter if d_j > thrN

    // Scan (all data L2-hot): gather hinge-overflow candidates
    for (int k = tid; k < NROWS; k += DTHREADS) {
        int   t  = targets[k];
        float dv = g_d[k];
        if (t == 1) {
            if (dv < thrP) {
                int idx = atomicAdd(&s_npl, 1);
                if (idx < MAXLIST) posList[idx] = dv;
            }
        } else {
            if (dv > thrN) {
                int idx = atomicAdd(&s_nnl, 1);
                if (idx < MAXLIST) negList[idx] = dv;
            }
        }
    }
    __syncthreads();

    const int npl = min(s_npl, MAXLIST);
    const int nnl = min(s_nnl, MAXLIST);

    // Exact correction: pos-striped, neg list serial per pos
    float corrF = 0.0f;
    for (int ip = tid; ip < npl; ip += DTHREADS) {
        const float dp = posList[ip] + MARGINF;
        float a = 0.0f;
        for (int jn = 0; jn < nnl; jn++) {
            a += fmaxf(negList[jn] - dp, 0.0f);
        }
        corrF += a;
    }
    double corr = (double)corrF;
    #pragma unroll
    for (int o = 16; o > 0; o >>= 1)
        corr += __shfl_xor_sync(0xFFFFFFFFu, corr, o);
    if ((tid & 31) == 0) redC[tid >> 5] = corr;
    __syncthreads();

    if (tid == 0) {
        double c = 0.0;
        #pragma unroll
        for (int w = 0; w < 8; w++) c += redC[w];
        double Sp = g_sp, Sn = g_sn;
        int    p  = g_np;
        double Np = (double)p;
        double Nn = (double)(NROWS - p);
        double linear = Nn * Sp - Np * Sn + (double)MARGINF * Np * Nn;
        out[0] = (float)((linear + c) / (Np * Nn));
        // reset for next graph replay
        g_sp = 0.0;
        g_sn = 0.0;
        g_np = 0;
        g_minpos = 0x7f800000;
        g_maxneg = 0;
        g_ticket = 0u;
    }
}

extern "C" void kernel_launch(void* const* d_in, const int* in_sizes, int n_in,
                              void* d_out, int out_size)
{
    const float* recon   = (const float*)d_in[0];
    const float* x       = (const float*)d_in[1];
    const int*   targets = (const int*)d_in[2];
    float* out = (float*)d_out;

    dist_kernel<<<NROWS, DTHREADS>>>(recon, x, targets, out);
}